// round 7
// baseline (speedup 1.0000x reference)
#include <cuda_runtime.h>
#include <cstddef>
#include <cstdint>

#define NN 100000
#define IN_DIM 256
#define H_DIM 128
#define C_DIM 40

// Scratch (device globals — no allocation allowed)
__device__ float g_h2[(size_t)NN * C_DIM];   // (relu(X@W1))@W2
__device__ float g_z1[(size_t)NN * C_DIM];   // first propagation
__device__ int   g_rowptr[NN + 1];           // CSR offsets from sorted edge_dst

// ---------------------------------------------------------------------------
// tf32 helpers
// ---------------------------------------------------------------------------
__device__ __forceinline__ float tf32r(float x) {
    uint32_t u;
    asm("cvt.rna.tf32.f32 %0, %1;" : "=r"(u) : "f"(x));
    return __uint_as_float(u);
}

__device__ __forceinline__ void mma_tf32(float* c, const uint32_t* a,
                                         uint32_t b0, uint32_t b1) {
    asm volatile(
        "mma.sync.aligned.m16n8k8.row.col.f32.tf32.tf32.f32 "
        "{%0,%1,%2,%3}, {%4,%5,%6,%7}, {%8,%9}, {%0,%1,%2,%3};\n"
        : "+f"(c[0]), "+f"(c[1]), "+f"(c[2]), "+f"(c[3])
        : "r"(a[0]), "r"(a[1]), "r"(a[2]), "r"(a[3]), "r"(b0), "r"(b1));
}

// ---------------------------------------------------------------------------
// Fused MLP: g_h2 = relu(X[M,256] @ W1[256,128]) @ W2[128,40]
// BM=64 x BN=128 tile, BK=32 double-buffered, 256 threads (8 warps).
// Warp tile 16x64 (acc = 32 regs) -> 3 CTAs/SM for latency hiding.
// Stage 2: warps 0-3 compute H[64,128] @ W2[128,40] in-block.
//
// smem (union):
//   stage1: As[2][64][36] (4608 f) | Bs[2][32][132] (8448 f) = 52224 B
//   stage2: H[64][132]    (8448 f) | Ws[128][44]    (5632 f) = 56320 B
// ---------------------------------------------------------------------------
#define S1_AS_STRIDE 36
#define S1_BS_STRIDE 132
#define S2_H_STRIDE 132
#define S2_W_STRIDE 44
#define FUSED_SMEM_BYTES 56320

extern __shared__ float sm[];

__global__ __launch_bounds__(256, 3) void fused_mlp_kernel(
    const float* __restrict__ A, const float* __restrict__ W1,
    const float* __restrict__ W2, int M) {
    const int tid = threadIdx.x;
    const int lane = tid & 31;
    const int wid = tid >> 5;
    const int blockRow = blockIdx.x;

    float* As = sm;                          // [2][64][36]
    float* Bs = sm + 2 * 64 * S1_AS_STRIDE;  // [2][32][132]

    const int warp_m = wid >> 1;   // 0..3 -> 16 rows each
    const int warp_n = wid & 1;    // 0..1 -> 64 cols each

    float acc[8][4];
    #pragma unroll
    for (int ni = 0; ni < 8; ni++)
        #pragma unroll
        for (int q = 0; q < 4; q++) acc[ni][q] = 0.f;

    // ---- prologue: k-tile 0 -> buffer 0 ----
    {
        #pragma unroll
        for (int t = 0; t < 2; t++) {        // A: 512 float4
            const int f4 = tid + t * 256;
            const int row = f4 >> 3, kc = (f4 & 7) * 4;
            float4 a4 = make_float4(0.f, 0.f, 0.f, 0.f);
            const int arow = blockRow * 64 + row;
            if (arow < M)
                a4 = *reinterpret_cast<const float4*>(A + (size_t)arow * IN_DIM + kc);
            float* p = As + row * S1_AS_STRIDE + kc;
            p[0] = tf32r(a4.x); p[1] = tf32r(a4.y);
            p[2] = tf32r(a4.z); p[3] = tf32r(a4.w);
        }
        #pragma unroll
        for (int t = 0; t < 4; t++) {        // B: 1024 float4
            const int f4 = tid + t * 256;
            const int bk = f4 >> 5, nc = (f4 & 31) * 4;
            float4 b4 = *reinterpret_cast<const float4*>(W1 + (size_t)bk * H_DIM + nc);
            float* q = Bs + bk * S1_BS_STRIDE + nc;
            q[0] = tf32r(b4.x); q[1] = tf32r(b4.y);
            q[2] = tf32r(b4.z); q[3] = tf32r(b4.w);
        }
    }
    __syncthreads();

    int cur = 0;
    constexpr int NKT = IN_DIM / 32;  // 8
    for (int kt = 0; kt < NKT; kt++) {
        float4 a_pref[2], b_pref[4];
        if (kt < NKT - 1) {
            const int k0 = (kt + 1) * 32;
            #pragma unroll
            for (int t = 0; t < 2; t++) {
                const int f4 = tid + t * 256;
                const int row = f4 >> 3, kc = (f4 & 7) * 4;
                const int arow = blockRow * 64 + row;
                a_pref[t] = make_float4(0.f, 0.f, 0.f, 0.f);
                if (arow < M)
                    a_pref[t] = *reinterpret_cast<const float4*>(
                        A + (size_t)arow * IN_DIM + k0 + kc);
            }
            #pragma unroll
            for (int t = 0; t < 4; t++) {
                const int f4 = tid + t * 256;
                const int bk = f4 >> 5, nc = (f4 & 31) * 4;
                b_pref[t] = *reinterpret_cast<const float4*>(
                    W1 + (size_t)(k0 + bk) * H_DIM + nc);
            }
        }

        const float* Ac = As + cur * 64 * S1_AS_STRIDE;
        const float* Bc = Bs + cur * 32 * S1_BS_STRIDE;
        #pragma unroll
        for (int k8 = 0; k8 < 4; k8++) {
            const int kk = k8 * 8;
            uint32_t af[4];
            const int rb = warp_m * 16 + (lane >> 2);
            const int kc = kk + (lane & 3);
            af[0] = __float_as_uint(Ac[rb * S1_AS_STRIDE + kc]);
            af[1] = __float_as_uint(Ac[(rb + 8) * S1_AS_STRIDE + kc]);
            af[2] = __float_as_uint(Ac[rb * S1_AS_STRIDE + kc + 4]);
            af[3] = __float_as_uint(Ac[(rb + 8) * S1_AS_STRIDE + kc + 4]);
            #pragma unroll
            for (int ni = 0; ni < 8; ni++) {
                const int nb = warp_n * 64 + ni * 8 + (lane >> 2);
                const uint32_t b0 =
                    __float_as_uint(Bc[(kk + (lane & 3)) * S1_BS_STRIDE + nb]);
                const uint32_t b1 =
                    __float_as_uint(Bc[(kk + 4 + (lane & 3)) * S1_BS_STRIDE + nb]);
                mma_tf32(acc[ni], af, b0, b1);
            }
        }

        if (kt < NKT - 1) {
            const int nxt = 1 - cur;
            float* An = As + nxt * 64 * S1_AS_STRIDE;
            float* Bn = Bs + nxt * 32 * S1_BS_STRIDE;
            #pragma unroll
            for (int t = 0; t < 2; t++) {
                const int f4 = tid + t * 256;
                const int row = f4 >> 3, kc = (f4 & 7) * 4;
                float* p = An + row * S1_AS_STRIDE + kc;
                p[0] = tf32r(a_pref[t].x); p[1] = tf32r(a_pref[t].y);
                p[2] = tf32r(a_pref[t].z); p[3] = tf32r(a_pref[t].w);
            }
            #pragma unroll
            for (int t = 0; t < 4; t++) {
                const int f4 = tid + t * 256;
                const int bk = f4 >> 5, nc = (f4 & 31) * 4;
                float* q = Bn + bk * S1_BS_STRIDE + nc;
                q[0] = tf32r(b_pref[t].x); q[1] = tf32r(b_pref[t].y);
                q[2] = tf32r(b_pref[t].z); q[3] = tf32r(b_pref[t].w);
            }
            __syncthreads();
            cur = nxt;
        }
    }

    // ---- stage 1 -> stage 2 transition ----
    __syncthreads();   // everyone done reading As/Bs before overlay

    float* H  = sm;                      // [64][132]
    float* Ws = sm + 64 * S2_H_STRIDE;   // [128][44]

    // relu + tf32 -> H tile in smem (each warp writes its 16x64 quadrant)
    {
        const int r0 = warp_m * 16 + (lane >> 2);
        #pragma unroll
        for (int ni = 0; ni < 8; ni++) {
            const int c0 = warp_n * 64 + ni * 8 + 2 * (lane & 3);
            H[r0 * S2_H_STRIDE + c0]           = tf32r(fmaxf(acc[ni][0], 0.f));
            H[r0 * S2_H_STRIDE + c0 + 1]       = tf32r(fmaxf(acc[ni][1], 0.f));
            H[(r0 + 8) * S2_H_STRIDE + c0]     = tf32r(fmaxf(acc[ni][2], 0.f));
            H[(r0 + 8) * S2_H_STRIDE + c0 + 1] = tf32r(fmaxf(acc[ni][3], 0.f));
        }
    }
    // load W2 [128][40] -> Ws
    for (int i = tid; i < H_DIM * C_DIM; i += 256)
        Ws[(i / C_DIM) * S2_W_STRIDE + (i % C_DIM)] = tf32r(W2[i]);
    __syncthreads();

    // ---- stage 2: warps 0-3, each 16 rows, K=128 ----
    if (wid < 4) {
        const int rb2 = wid * 16;
        float acc2[5][4];
        #pragma unroll
        for (int ni = 0; ni < 5; ni++)
            #pragma unroll
            for (int q = 0; q < 4; q++) acc2[ni][q] = 0.f;

        #pragma unroll
        for (int k8 = 0; k8 < 16; k8++) {
            const int kk = k8 * 8;
            uint32_t af[4];
            const int rr = rb2 + (lane >> 2);
            const int kc = kk + (lane & 3);
            af[0] = __float_as_uint(H[rr * S2_H_STRIDE + kc]);
            af[1] = __float_as_uint(H[(rr + 8) * S2_H_STRIDE + kc]);
            af[2] = __float_as_uint(H[rr * S2_H_STRIDE + kc + 4]);
            af[3] = __float_as_uint(H[(rr + 8) * S2_H_STRIDE + kc + 4]);
            #pragma unroll
            for (int ni = 0; ni < 5; ni++) {
                const int nb = ni * 8 + (lane >> 2);
                const uint32_t b0 =
                    __float_as_uint(Ws[(kk + (lane & 3)) * S2_W_STRIDE + nb]);
                const uint32_t b1 =
                    __float_as_uint(Ws[(kk + 4 + (lane & 3)) * S2_W_STRIDE + nb]);
                mma_tf32(acc2[ni], af, b0, b1);
            }
        }

        const int row0 = blockRow * 64 + rb2 + (lane >> 2);
        #pragma unroll
        for (int ni = 0; ni < 5; ni++) {
            const int c0 = ni * 8 + 2 * (lane & 3);
            if (row0 < M) {
                float2 v = make_float2(acc2[ni][0], acc2[ni][1]);
                *reinterpret_cast<float2*>(g_h2 + (size_t)row0 * C_DIM + c0) = v;
            }
            if (row0 + 8 < M) {
                float2 v = make_float2(acc2[ni][2], acc2[ni][3]);
                *reinterpret_cast<float2*>(g_h2 + (size_t)(row0 + 8) * C_DIM + c0) = v;
            }
        }
    }
}

// ---------------------------------------------------------------------------
// Row-pointer build: edge_dst is SORTED. rowptr[v] = lower_bound(dst, v).
// ---------------------------------------------------------------------------
__global__ void rowptr_kernel(const int* __restrict__ dst, int N, int E) {
    const int v = blockIdx.x * blockDim.x + threadIdx.x;
    if (v > N) return;
    int lo = 0, hi = E;
    while (lo < hi) {
        const int mid = (lo + hi) >> 1;
        if (__ldg(dst + mid) < v) lo = mid + 1; else hi = mid;
    }
    g_rowptr[v] = lo;
}

// ---------------------------------------------------------------------------
// CSR SPMM (exact Round-4 config — best measured: 37.1 us):
// 320 threads = 32 groups x 10 lanes; group owns one node; lane owns float4.
// 2-edge unroll. No atomics, no output zeroing.
// ---------------------------------------------------------------------------
__global__ __launch_bounds__(320) void spmm_csr_kernel(
    const int* __restrict__ src, const float* __restrict__ val,
    const float* __restrict__ x, float* __restrict__ out, int N) {
    const int tid = threadIdx.x;
    const int node = blockIdx.x * 32 + tid / 10;
    const int lane = tid % 10;
    if (node >= N) return;

    const int start = __ldg(g_rowptr + node);
    const int end   = __ldg(g_rowptr + node + 1);

    float4 a0 = make_float4(0.f, 0.f, 0.f, 0.f);
    float4 a1 = make_float4(0.f, 0.f, 0.f, 0.f);

    int i = start;
    for (; i + 2 <= end; i += 2) {
        const int   s0 = __ldg(src + i);
        const int   s1 = __ldg(src + i + 1);
        const float v0 = __ldg(val + i);
        const float v1 = __ldg(val + i + 1);
        const float4 x0 = *reinterpret_cast<const float4*>(
            x + (size_t)s0 * C_DIM + lane * 4);
        const float4 x1 = *reinterpret_cast<const float4*>(
            x + (size_t)s1 * C_DIM + lane * 4);
        a0.x = fmaf(v0, x0.x, a0.x); a0.y = fmaf(v0, x0.y, a0.y);
        a0.z = fmaf(v0, x0.z, a0.z); a0.w = fmaf(v0, x0.w, a0.w);
        a1.x = fmaf(v1, x1.x, a1.x); a1.y = fmaf(v1, x1.y, a1.y);
        a1.z = fmaf(v1, x1.z, a1.z); a1.w = fmaf(v1, x1.w, a1.w);
    }
    if (i < end) {
        const int   s0 = __ldg(src + i);
        const float v0 = __ldg(val + i);
        const float4 x0 = *reinterpret_cast<const float4*>(
            x + (size_t)s0 * C_DIM + lane * 4);
        a0.x = fmaf(v0, x0.x, a0.x); a0.y = fmaf(v0, x0.y, a0.y);
        a0.z = fmaf(v0, x0.z, a0.z); a0.w = fmaf(v0, x0.w, a0.w);
    }

    float4 r;
    r.x = a0.x + a1.x; r.y = a0.y + a1.y;
    r.z = a0.z + a1.z; r.w = a0.w + a1.w;
    *reinterpret_cast<float4*>(out + (size_t)node * C_DIM + lane * 4) = r;
}

extern "C" void kernel_launch(void* const* d_in, const int* in_sizes, int n_in,
                              void* d_out, int out_size) {
    const float* features = (const float*)d_in[0];
    const float* W1       = (const float*)d_in[1];
    const float* W2       = (const float*)d_in[2];
    const int*   edge_src = (const int*)d_in[3];
    const int*   edge_dst = (const int*)d_in[4];
    const float* edge_val = (const float*)d_in[5];
    float* out = (float*)d_out;

    const int M = in_sizes[0] / IN_DIM;   // 100000
    const int E = in_sizes[3];            // 1600000

    float *p_h2, *p_z1;
    cudaGetSymbolAddress((void**)&p_h2, g_h2);
    cudaGetSymbolAddress((void**)&p_z1, g_z1);

    static bool attr_set = false;
    if (!attr_set) {
        cudaFuncSetAttribute(fused_mlp_kernel,
                             cudaFuncAttributeMaxDynamicSharedMemorySize,
                             FUSED_SMEM_BYTES);
        attr_set = true;
    }

    // 1) h2 = relu(X @ W1) @ W2  (single fused kernel)
    fused_mlp_kernel<<<(M + 63) / 64, 256, FUSED_SMEM_BYTES>>>(
        features, W1, W2, M);

    // 2) CSR row pointers from sorted edge_dst (shared by both propagations)
    rowptr_kernel<<<(M + 257) / 256, 256>>>(edge_dst, M, E);

    // 3) z1 = A @ h2 ; out = A @ z1   (no zeroing, no atomics)
    spmm_csr_kernel<<<(M + 31) / 32, 320>>>(edge_src, edge_val, p_h2, p_z1, M);
    spmm_csr_kernel<<<(M + 31) / 32, 320>>>(edge_src, edge_val, p_z1, out, M);
}

// round 8
// speedup vs baseline: 1.1591x; 1.1591x over previous
#include <cuda_runtime.h>
#include <cstddef>
#include <cstdint>

#define NN 100000
#define IN_DIM 256
#define H_DIM 128
#define C_DIM 40

// Scratch (device globals — no allocation allowed)
__device__ float g_h2[(size_t)NN * C_DIM];   // (relu(X@W1))@W2
__device__ float g_z1[(size_t)NN * C_DIM];   // first propagation
__device__ int   g_rowptr[NN + 1];           // CSR offsets from sorted edge_dst

// ---------------------------------------------------------------------------
// tf32 helpers
// ---------------------------------------------------------------------------
__device__ __forceinline__ float tf32r(float x) {
    uint32_t u;
    asm("cvt.rna.tf32.f32 %0, %1;" : "=r"(u) : "f"(x));
    return __uint_as_float(u);
}

__device__ __forceinline__ void mma_tf32(float* c, const uint32_t* a,
                                         uint32_t b0, uint32_t b1) {
    asm volatile(
        "mma.sync.aligned.m16n8k8.row.col.f32.tf32.tf32.f32 "
        "{%0,%1,%2,%3}, {%4,%5,%6,%7}, {%8,%9}, {%0,%1,%2,%3};\n"
        : "+f"(c[0]), "+f"(c[1]), "+f"(c[2]), "+f"(c[3])
        : "r"(a[0]), "r"(a[1]), "r"(a[2]), "r"(a[3]), "r"(b0), "r"(b1));
}

// ---------------------------------------------------------------------------
// Fused MLP: g_h2 = relu(X[M,256] @ W1[256,128]) @ W2[128,40]
// R3 shape (BM=128, warp tile 32x64, BK=32 double-buffered, 8 warps) with
// Bs stride 132 -> 136 (mod 32 == 8) so B-fragment LDS bank = 8*(lane&3) +
// (lane>>2): bijective over lanes => conflict-free.
//
// smem (union):
//   stage1: As[2][128][36] (9216 f) | Bs[2][32][136] (8704 f) = 71680 B
//   stage2: H[128][132]   (16896 f) | Ws[128][44]    (5632 f) = 90112 B
// ---------------------------------------------------------------------------
#define S1_AS_STRIDE 36
#define S1_BS_STRIDE 136
#define S2_H_STRIDE 132
#define S2_W_STRIDE 44
#define FUSED_SMEM_BYTES 90112

extern __shared__ float sm[];

__global__ __launch_bounds__(256) void fused_mlp_kernel(
    const float* __restrict__ A, const float* __restrict__ W1,
    const float* __restrict__ W2, int M) {
    const int tid = threadIdx.x;
    const int lane = tid & 31;
    const int wid = tid >> 5;
    const int blockRow = blockIdx.x;

    float* As = sm;                           // [2][128][36]
    float* Bs = sm + 2 * 128 * S1_AS_STRIDE;  // [2][32][136]

    const int warp_m = wid >> 1;   // 0..3 -> 32 rows each
    const int warp_n = wid & 1;    // 0..1 -> 64 cols each

    float acc[2][8][4];
    #pragma unroll
    for (int mi = 0; mi < 2; mi++)
        #pragma unroll
        for (int ni = 0; ni < 8; ni++)
            #pragma unroll
            for (int q = 0; q < 4; q++) acc[mi][ni][q] = 0.f;

    // ---- prologue: k-tile 0 -> buffer 0 ----
    {
        #pragma unroll
        for (int t = 0; t < 4; t++) {
            const int f4 = tid + t * 256;
            const int row = f4 >> 3, kc = (f4 & 7) * 4;
            float4 a4 = make_float4(0.f, 0.f, 0.f, 0.f);
            const int arow = blockRow * 128 + row;
            if (arow < M)
                a4 = *reinterpret_cast<const float4*>(A + (size_t)arow * IN_DIM + kc);
            float* p = As + row * S1_AS_STRIDE + kc;
            p[0] = tf32r(a4.x); p[1] = tf32r(a4.y);
            p[2] = tf32r(a4.z); p[3] = tf32r(a4.w);
            const int bk = f4 >> 5, nc = (f4 & 31) * 4;
            float4 b4 = *reinterpret_cast<const float4*>(W1 + (size_t)bk * H_DIM + nc);
            float* q = Bs + bk * S1_BS_STRIDE + nc;
            q[0] = tf32r(b4.x); q[1] = tf32r(b4.y);
            q[2] = tf32r(b4.z); q[3] = tf32r(b4.w);
        }
    }
    __syncthreads();

    int cur = 0;
    constexpr int NKT = IN_DIM / 32;  // 8
    for (int kt = 0; kt < NKT; kt++) {
        float4 a_pref[4], b_pref[4];
        if (kt < NKT - 1) {
            const int k0 = (kt + 1) * 32;
            #pragma unroll
            for (int t = 0; t < 4; t++) {
                const int f4 = tid + t * 256;
                const int row = f4 >> 3, kc = (f4 & 7) * 4;
                const int arow = blockRow * 128 + row;
                a_pref[t] = make_float4(0.f, 0.f, 0.f, 0.f);
                if (arow < M)
                    a_pref[t] = *reinterpret_cast<const float4*>(
                        A + (size_t)arow * IN_DIM + k0 + kc);
                const int bk = f4 >> 5, nc = (f4 & 31) * 4;
                b_pref[t] = *reinterpret_cast<const float4*>(
                    W1 + (size_t)(k0 + bk) * H_DIM + nc);
            }
        }

        const float* Ac = As + cur * 128 * S1_AS_STRIDE;
        const float* Bc = Bs + cur * 32 * S1_BS_STRIDE;
        #pragma unroll
        for (int k8 = 0; k8 < 4; k8++) {
            const int kk = k8 * 8;
            uint32_t af[2][4];
            #pragma unroll
            for (int mi = 0; mi < 2; mi++) {
                const int rb = warp_m * 32 + mi * 16 + (lane >> 2);
                const int kc = kk + (lane & 3);
                af[mi][0] = __float_as_uint(Ac[rb * S1_AS_STRIDE + kc]);
                af[mi][1] = __float_as_uint(Ac[(rb + 8) * S1_AS_STRIDE + kc]);
                af[mi][2] = __float_as_uint(Ac[rb * S1_AS_STRIDE + kc + 4]);
                af[mi][3] = __float_as_uint(Ac[(rb + 8) * S1_AS_STRIDE + kc + 4]);
            }
            #pragma unroll
            for (int ni = 0; ni < 8; ni++) {
                const int nb = warp_n * 64 + ni * 8 + (lane >> 2);
                const uint32_t b0 =
                    __float_as_uint(Bc[(kk + (lane & 3)) * S1_BS_STRIDE + nb]);
                const uint32_t b1 =
                    __float_as_uint(Bc[(kk + 4 + (lane & 3)) * S1_BS_STRIDE + nb]);
                mma_tf32(acc[0][ni], af[0], b0, b1);
                mma_tf32(acc[1][ni], af[1], b0, b1);
            }
        }

        if (kt < NKT - 1) {
            const int nxt = 1 - cur;
            float* An = As + nxt * 128 * S1_AS_STRIDE;
            float* Bn = Bs + nxt * 32 * S1_BS_STRIDE;
            #pragma unroll
            for (int t = 0; t < 4; t++) {
                const int f4 = tid + t * 256;
                const int row = f4 >> 3, kc = (f4 & 7) * 4;
                float* p = An + row * S1_AS_STRIDE + kc;
                p[0] = tf32r(a_pref[t].x); p[1] = tf32r(a_pref[t].y);
                p[2] = tf32r(a_pref[t].z); p[3] = tf32r(a_pref[t].w);
                const int bk = f4 >> 5, nc = (f4 & 31) * 4;
                float* q = Bn + bk * S1_BS_STRIDE + nc;
                q[0] = tf32r(b_pref[t].x); q[1] = tf32r(b_pref[t].y);
                q[2] = tf32r(b_pref[t].z); q[3] = tf32r(b_pref[t].w);
            }
            __syncthreads();
            cur = nxt;
        }
    }

    // ---- stage 1 -> stage 2 transition ----
    __syncthreads();

    float* H  = sm;                      // [128][132]
    float* Ws = sm + 128 * S2_H_STRIDE;  // [128][44]

    #pragma unroll
    for (int mi = 0; mi < 2; mi++) {
        const int r0 = warp_m * 32 + mi * 16 + (lane >> 2);
        #pragma unroll
        for (int ni = 0; ni < 8; ni++) {
            const int c0 = warp_n * 64 + ni * 8 + 2 * (lane & 3);
            H[r0 * S2_H_STRIDE + c0]           = tf32r(fmaxf(acc[mi][ni][0], 0.f));
            H[r0 * S2_H_STRIDE + c0 + 1]       = tf32r(fmaxf(acc[mi][ni][1], 0.f));
            H[(r0 + 8) * S2_H_STRIDE + c0]     = tf32r(fmaxf(acc[mi][ni][2], 0.f));
            H[(r0 + 8) * S2_H_STRIDE + c0 + 1] = tf32r(fmaxf(acc[mi][ni][3], 0.f));
        }
    }
    for (int i = tid; i < H_DIM * C_DIM; i += 256)
        Ws[(i / C_DIM) * S2_W_STRIDE + (i % C_DIM)] = tf32r(W2[i]);
    __syncthreads();

    const int rb2 = wid * 16;
    float acc2[5][4];
    #pragma unroll
    for (int ni = 0; ni < 5; ni++)
        #pragma unroll
        for (int q = 0; q < 4; q++) acc2[ni][q] = 0.f;

    #pragma unroll
    for (int k8 = 0; k8 < 16; k8++) {
        const int kk = k8 * 8;
        uint32_t af[4];
        const int rr = rb2 + (lane >> 2);
        const int kc = kk + (lane & 3);
        af[0] = __float_as_uint(H[rr * S2_H_STRIDE + kc]);
        af[1] = __float_as_uint(H[(rr + 8) * S2_H_STRIDE + kc]);
        af[2] = __float_as_uint(H[rr * S2_H_STRIDE + kc + 4]);
        af[3] = __float_as_uint(H[(rr + 8) * S2_H_STRIDE + kc + 4]);
        #pragma unroll
        for (int ni = 0; ni < 5; ni++) {
            const int nb = ni * 8 + (lane >> 2);
            const uint32_t b0 =
                __float_as_uint(Ws[(kk + (lane & 3)) * S2_W_STRIDE + nb]);
            const uint32_t b1 =
                __float_as_uint(Ws[(kk + 4 + (lane & 3)) * S2_W_STRIDE + nb]);
            mma_tf32(acc2[ni], af, b0, b1);
        }
    }

    const int row0 = blockRow * 128 + rb2 + (lane >> 2);
    #pragma unroll
    for (int ni = 0; ni < 5; ni++) {
        const int c0 = ni * 8 + 2 * (lane & 3);
        if (row0 < M) {
            float2 v = make_float2(acc2[ni][0], acc2[ni][1]);
            *reinterpret_cast<float2*>(g_h2 + (size_t)row0 * C_DIM + c0) = v;
        }
        if (row0 + 8 < M) {
            float2 v = make_float2(acc2[ni][2], acc2[ni][3]);
            *reinterpret_cast<float2*>(g_h2 + (size_t)(row0 + 8) * C_DIM + c0) = v;
        }
    }
}

// ---------------------------------------------------------------------------
// Row-pointer build: edge_dst is SORTED. rowptr[v] = lower_bound(dst, v).
// ---------------------------------------------------------------------------
__global__ void rowptr_kernel(const int* __restrict__ dst, int N, int E) {
    const int v = blockIdx.x * blockDim.x + threadIdx.x;
    if (v > N) return;
    int lo = 0, hi = E;
    while (lo < hi) {
        const int mid = (lo + hi) >> 1;
        if (__ldg(dst + mid) < v) lo = mid + 1; else hi = mid;
    }
    g_rowptr[v] = lo;
}

// ---------------------------------------------------------------------------
// CSR SPMM (exact Round-4 config — best measured: 36.9-37.1 us):
// 320 threads = 32 groups x 10 lanes; group owns one node; lane owns float4.
// 2-edge unroll. No atomics, no output zeroing.
// ---------------------------------------------------------------------------
__global__ __launch_bounds__(320) void spmm_csr_kernel(
    const int* __restrict__ src, const float* __restrict__ val,
    const float* __restrict__ x, float* __restrict__ out, int N) {
    const int tid = threadIdx.x;
    const int node = blockIdx.x * 32 + tid / 10;
    const int lane = tid % 10;
    if (node >= N) return;

    const int start = __ldg(g_rowptr + node);
    const int end   = __ldg(g_rowptr + node + 1);

    float4 a0 = make_float4(0.f, 0.f, 0.f, 0.f);
    float4 a1 = make_float4(0.f, 0.f, 0.f, 0.f);

    int i = start;
    for (; i + 2 <= end; i += 2) {
        const int   s0 = __ldg(src + i);
        const int   s1 = __ldg(src + i + 1);
        const float v0 = __ldg(val + i);
        const float v1 = __ldg(val + i + 1);
        const float4 x0 = *reinterpret_cast<const float4*>(
            x + (size_t)s0 * C_DIM + lane * 4);
        const float4 x1 = *reinterpret_cast<const float4*>(
            x + (size_t)s1 * C_DIM + lane * 4);
        a0.x = fmaf(v0, x0.x, a0.x); a0.y = fmaf(v0, x0.y, a0.y);
        a0.z = fmaf(v0, x0.z, a0.z); a0.w = fmaf(v0, x0.w, a0.w);
        a1.x = fmaf(v1, x1.x, a1.x); a1.y = fmaf(v1, x1.y, a1.y);
        a1.z = fmaf(v1, x1.z, a1.z); a1.w = fmaf(v1, x1.w, a1.w);
    }
    if (i < end) {
        const int   s0 = __ldg(src + i);
        const float v0 = __ldg(val + i);
        const float4 x0 = *reinterpret_cast<const float4*>(
            x + (size_t)s0 * C_DIM + lane * 4);
        a0.x = fmaf(v0, x0.x, a0.x); a0.y = fmaf(v0, x0.y, a0.y);
        a0.z = fmaf(v0, x0.z, a0.z); a0.w = fmaf(v0, x0.w, a0.w);
    }

    float4 r;
    r.x = a0.x + a1.x; r.y = a0.y + a1.y;
    r.z = a0.z + a1.z; r.w = a0.w + a1.w;
    *reinterpret_cast<float4*>(out + (size_t)node * C_DIM + lane * 4) = r;
}

extern "C" void kernel_launch(void* const* d_in, const int* in_sizes, int n_in,
                              void* d_out, int out_size) {
    const float* features = (const float*)d_in[0];
    const float* W1       = (const float*)d_in[1];
    const float* W2       = (const float*)d_in[2];
    const int*   edge_src = (const int*)d_in[3];
    const int*   edge_dst = (const int*)d_in[4];
    const float* edge_val = (const float*)d_in[5];
    float* out = (float*)d_out;

    const int M = in_sizes[0] / IN_DIM;   // 100000
    const int E = in_sizes[3];            // 1600000

    float *p_h2, *p_z1;
    cudaGetSymbolAddress((void**)&p_h2, g_h2);
    cudaGetSymbolAddress((void**)&p_z1, g_z1);

    static bool attr_set = false;
    if (!attr_set) {
        cudaFuncSetAttribute(fused_mlp_kernel,
                             cudaFuncAttributeMaxDynamicSharedMemorySize,
                             FUSED_SMEM_BYTES);
        attr_set = true;
    }

    // 1) h2 = relu(X @ W1) @ W2  (single fused kernel)
    fused_mlp_kernel<<<(M + 127) / 128, 256, FUSED_SMEM_BYTES>>>(
        features, W1, W2, M);

    // 2) CSR row pointers from sorted edge_dst (shared by both propagations)
    rowptr_kernel<<<(M + 257) / 256, 256>>>(edge_dst, M, E);

    // 3) z1 = A @ h2 ; out = A @ z1   (no zeroing, no atomics)
    spmm_csr_kernel<<<(M + 31) / 32, 320>>>(edge_src, edge_val, p_h2, p_z1, M);
    spmm_csr_kernel<<<(M + 31) / 32, 320>>>(edge_src, edge_val, p_z1, out, M);
}